// round 9
// baseline (speedup 1.0000x reference)
#include <cuda_runtime.h>

// PINN_Difference_RNN — parallel-in-time decayed-carry scan.
// R8: (1) sOut overlaid on u-planes (u held in regs across phases) -> 26 KB smem,
//     (2) single LDS pass for u inputs, (3) phase-1 chain split 16 -> 2x8 via A^8.

constexpr int TPB   = 128;
constexpr int LT    = 16;          // elements per thread (4 float4s)
constexpr int CHUNK = TPB * LT;    // 2048 elements per block

// u planes: 512 float4 each inside sA. Thread o owns slots [4o,4o+4) of a plane.
__device__ __forceinline__ int idxU(int o, int s) {
    return o * 4 + ((s ^ o ^ (o >> 2)) & 3);
}
// out overlay: 1024 float4 over all of sA. Thread o owns [8o,8o+8).
__device__ __forceinline__ int idxO(int o, int j) {
    return o * 8 + ((j ^ o) & 7);
}

__global__ __launch_bounds__(TPB, 6)
void pinn_rnn_kernel(const float* __restrict__ x0_in,
                     const float* __restrict__ u,
                     const float* __restrict__ dtv,
                     const float* __restrict__ WA,
                     const float* __restrict__ bA,
                     const float* __restrict__ WB,
                     const float* __restrict__ bB,
                     float* __restrict__ out,
                     int T)
{
    __shared__ float4 sA[CHUNK / 2];       // 16 KB: [0:512)=u0 plane, [512:1024)=u1 plane; later: out overlay
    __shared__ float4 sDT[CHUNK / 4];      // 8 KB
    __shared__ float2 sC[TPB + 3];         // ghost + per-thread carries

    const int tid   = threadIdx.x;
    const int chunk = blockIdx.x * CHUNK;

    const float a00 = WA[0], a01 = WA[1], a10 = WA[2], a11 = WA[3];
    const float w00 = WB[0], w01 = WB[1], w10 = WB[2], w11 = WB[3];
    const float cb0 = bA[0] + bB[0];
    const float cb1 = bA[1] + bB[1];

    const float* __restrict__ U0 = u;
    const float* __restrict__ U1 = u + T;

#define STEPV(xa, xb, U0v, U1v)                                     \
    do {                                                            \
        float v0 = fmaf(w00, (U0v), fmaf(w01, (U1v), cb0));         \
        float v1 = fmaf(w10, (U0v), fmaf(w11, (U1v), cb1));         \
        float n0 = fmaf(a00, xa, fmaf(a01, xb, v0));                \
        float n1 = fmaf(a10, xa, fmaf(a11, xb, v1));                \
        xa = n0; xb = n1;                                           \
    } while (0)

    // ---- Stage u0/u1/dt: coalesced LDG.128, swizzled STS.128 ---------------
    {
        const float4* g0 = reinterpret_cast<const float4*>(U0 + chunk);
        const float4* g1 = reinterpret_cast<const float4*>(U1 + chunk);
        const float4* gd = reinterpret_cast<const float4*>(dtv + chunk);
#pragma unroll
        for (int k = 0; k < 4; k++) {
            int f = k * TPB + tid;            // float4 index in chunk (0..511)
            int o = f >> 2, s = f & 3;
            int a = idxU(o, s);
            sA[a]       = g0[f];
            sA[512 + a] = g1[f];
            sDT[a]      = gd[f];
        }
    }

    // ---- Ghost carries: zero-init scans of the 3 preceding sub-chunks ------
    if (tid < 3) {
        if (chunk == 0) {
            if (tid == 0) {
                sC[2] = make_float2(x0_in[0], x0_in[1]);   // exact x_0
                sC[1] = make_float2(0.f, 0.f);
                sC[0] = make_float2(0.f, 0.f);
            }
        } else {
            int start = chunk - LT * (tid + 1);
            float ga = 0.f, gb = 0.f;
#pragma unroll
            for (int i = 0; i < LT; i++) {
                float u0v = U0[start + i];
                float u1v = U1[start + i];
                STEPV(ga, gb, u0v, u1v);
            }
            sC[2 - tid] = make_float2(ga, gb);
        }
    }
    __syncthreads();

    // ---- Load own u data ONCE into registers (kept for both phases) --------
    float4 p[4], q[4];
#pragma unroll
    for (int s = 0; s < 4; s++) {
        p[s] = sA[idxU(tid, s)];
        q[s] = sA[512 + idxU(tid, s)];
    }

    // ---- Phase 1: two independent 8-step zero-init chains (ILP=2) ----------
    float la = 0.f, lb = 0.f;   // steps 0..7  (slots 0,1)
    float ha = 0.f, hb = 0.f;   // steps 8..15 (slots 2,3)
#pragma unroll
    for (int s = 0; s < 2; s++) {
        STEPV(la, lb, p[s].x, q[s].x);   STEPV(ha, hb, p[s+2].x, q[s+2].x);
        STEPV(la, lb, p[s].y, q[s].y);   STEPV(ha, hb, p[s+2].y, q[s+2].y);
        STEPV(la, lb, p[s].z, q[s].z);   STEPV(ha, hb, p[s+2].z, q[s+2].z);
        STEPV(la, lb, p[s].w, q[s].w);   STEPV(ha, hb, p[s+2].w, q[s+2].w);
    }

    // ---- Squaring ladder: A^2 -> A^4 -> A^8 --------------------------------
    float m00 = a00, m01 = a01, m10 = a10, m11 = a11;
#pragma unroll
    for (int s = 0; s < 3; s++) {
        float tr  = m00 + m11;
        float det = m01 * m10;
        float t00 = fmaf(m00, m00, det);
        float t01 = m01 * tr;
        float t10 = m10 * tr;
        float t11 = fmaf(m11, m11, det);
        m00 = t00; m01 = t01; m10 = t10; m11 = t11;
    }
    // c_thread = c_hi + A^8 * c_lo   (linear superposition, exact)
    {
        float ca = ha + fmaf(m00, la, m01 * lb);
        float cb = hb + fmaf(m10, la, m11 * lb);
        sC[3 + tid] = make_float2(ca, cb);
    }
    // continue ladder: A^16, A^32
    {
        float tr  = m00 + m11;
        float det = m01 * m10;
        float t00 = fmaf(m00, m00, det);
        float t01 = m01 * tr;
        float t10 = m10 * tr;
        float t11 = fmaf(m11, m11, det);
        m00 = t00; m01 = t01; m10 = t10; m11 = t11;   // A^16
    }
    float trp  = m00 + m11;
    float detp = m01 * m10;
    float p00 = fmaf(m00, m00, detp);                 // A^32
    float p01 = m01 * trp;
    float p10 = m10 * trp;
    float p11 = fmaf(m11, m11, detp);

    __syncthreads();   // sC ready; also: all sA reads done -> overlay safe below

    // ---- Carry combine: S = c_{i-1} + A^16 c_{i-2} + A^32 c_{i-3} ----------
    float2 cA = sC[tid + 2];
    float2 cB = sC[tid + 1];
    float2 cC = sC[tid];
    float xa = cA.x + fmaf(m00, cB.x, fmaf(m01, cB.y, fmaf(p00, cC.x, p01 * cC.y)));
    float xb = cA.y + fmaf(m10, cB.x, fmaf(m11, cB.y, fmaf(p10, cC.x, p11 * cC.y)));

    // ---- Phase 2: rescan from regs; outputs -> overlay plane (sA) ----------
#pragma unroll
    for (int s = 0; s < 4; s++) {
        float4 d = sDT[idxU(tid, s)];
        float4 oA, oB;
#define EMIT(U0v, U1v, DTv, O0, O1)                                 \
        do {                                                        \
            float pre0 = xa, pre1 = xb;                             \
            STEPV(xa, xb, U0v, U1v);                                \
            float s_, c_;                                           \
            __sincosf((U1v), &s_, &c_);                             \
            float cc = (U0v) * (DTv);                               \
            O0 = fmaf(cc, c_, pre0) - xa;                           \
            O1 = fmaf(cc, s_, pre1) - xb;                           \
        } while (0)
        EMIT(p[s].x, q[s].x, d.x, oA.x, oA.y);
        EMIT(p[s].y, q[s].y, d.y, oA.z, oA.w);
        EMIT(p[s].z, q[s].z, d.z, oB.x, oB.y);
        EMIT(p[s].w, q[s].w, d.w, oB.z, oB.w);
#undef EMIT
        sA[idxO(tid, 2 * s)]     = oA;
        sA[idxO(tid, 2 * s + 1)] = oB;
    }
    __syncthreads();

    // ---- Coalesced STG.128 of outputs --------------------------------------
    {
        float4* og = reinterpret_cast<float4*>(out + 2 * chunk);
#pragma unroll
        for (int k = 0; k < 8; k++) {
            int h = k * TPB + tid;            // output float4 index (0..1023)
            og[h] = sA[idxO(h >> 3, h & 7)];
        }
    }
#undef STEPV
}

extern "C" void kernel_launch(void* const* d_in, const int* in_sizes, int n_in,
                              void* d_out, int out_size)
{
    const float* x0 = (const float*)d_in[0];   // (1,2)
    const float* u  = (const float*)d_in[1];   // (2,T)
    const float* dt = (const float*)d_in[2];   // (T,)
    const float* WA = (const float*)d_in[3];   // (2,2)
    const float* bA = (const float*)d_in[4];   // (2,)
    const float* WB = (const float*)d_in[5];   // (2,2)
    const float* bB = (const float*)d_in[6];   // (2,)
    float* out = (float*)d_out;                // (T,2)

    int T = in_sizes[2];
    int grid = (T + CHUNK - 1) / CHUNK;        // 2^22 / 2048 = 2048 blocks

    pinn_rnn_kernel<<<grid, TPB>>>(x0, u, dt, WA, bA, WB, bB, out, T);
}

// round 14
// speedup vs baseline: 1.0019x; 1.0019x over previous
#include <cuda_runtime.h>

// PINN_Difference_RNN — parallel-in-time decayed-carry scan.
// R10: LT 16->8 to halve serial chains and double occupancy (latency-bound fix).
// Carry window extended to 6 terms (A^48 truncation, same bound as before).

constexpr int TPB   = 128;
constexpr int LT    = 8;           // elements per thread (2 float4s)
constexpr int CHUNK = TPB * LT;    // 1024 elements per block
constexpr int NGH   = 6;           // ghost carries (A^48 truncation)

// u/dt planes: 256 float4. Thread o owns slots {2o, 2o+1}.
__device__ __forceinline__ int idxU(int o, int s) {
    return o * 2 + (((o >> 2) ^ s) & 1);
}
// out overlay: 512 float4. Thread o owns [4o, 4o+4).
__device__ __forceinline__ int idxO(int o, int j) {
    return o * 4 + (((o >> 1) ^ j) & 3);
}

// 2x2 matmul: R = X * Y (row-major [00 01; 10 11])
#define MATMUL(R00,R01,R10,R11, X00,X01,X10,X11, Y00,Y01,Y10,Y11)   \
    do {                                                            \
        R00 = fmaf(X00, Y00, X01 * Y10);                            \
        R01 = fmaf(X00, Y01, X01 * Y11);                            \
        R10 = fmaf(X10, Y00, X11 * Y10);                            \
        R11 = fmaf(X10, Y01, X11 * Y11);                            \
    } while (0)

__global__ __launch_bounds__(TPB, 7)
void pinn_rnn_kernel(const float* __restrict__ x0_in,
                     const float* __restrict__ u,
                     const float* __restrict__ dtv,
                     const float* __restrict__ WA,
                     const float* __restrict__ bA,
                     const float* __restrict__ WB,
                     const float* __restrict__ bB,
                     float* __restrict__ out,
                     int T)
{
    __shared__ float4 sA[CHUNK / 2];       // 8 KB: [0,256)=u0, [256,512)=u1; later out overlay
    __shared__ float4 sDT[CHUNK / 4];      // 4 KB
    __shared__ float2 sC[TPB + NGH];       // ghosts [0..5] = c_{-6..-1}, [6+i] = c_i

    const int tid   = threadIdx.x;
    const int chunk = blockIdx.x * CHUNK;

    const float a00 = WA[0], a01 = WA[1], a10 = WA[2], a11 = WA[3];
    const float w00 = WB[0], w01 = WB[1], w10 = WB[2], w11 = WB[3];
    const float cb0 = bA[0] + bB[0];
    const float cb1 = bA[1] + bB[1];

    const float* __restrict__ U0 = u;
    const float* __restrict__ U1 = u + T;

#define STEPV(xa, xb, U0v, U1v)                                     \
    do {                                                            \
        float v0 = fmaf(w00, (U0v), fmaf(w01, (U1v), cb0));         \
        float v1 = fmaf(w10, (U0v), fmaf(w11, (U1v), cb1));         \
        float n0 = fmaf(a00, xa, fmaf(a01, xb, v0));                \
        float n1 = fmaf(a10, xa, fmaf(a11, xb, v1));                \
        xa = n0; xb = n1;                                           \
    } while (0)

    // ---- Stage u0/u1/dt: coalesced LDG.128, swizzled STS.128 ---------------
    {
        const float4* g0 = reinterpret_cast<const float4*>(U0 + chunk);
        const float4* g1 = reinterpret_cast<const float4*>(U1 + chunk);
        const float4* gd = reinterpret_cast<const float4*>(dtv + chunk);
#pragma unroll
        for (int k = 0; k < 2; k++) {
            int f = k * TPB + tid;            // 0..255
            int o = f >> 1, s = f & 1;
            int a = idxU(o, s);
            sA[a]       = g0[f];
            sA[256 + a] = g1[f];
            sDT[a]      = gd[f];
        }
    }

    // ---- Ghost carries: zero-init scans of the 6 preceding sub-chunks ------
    if (tid < NGH) {
        if (chunk == 0) {
            // exact x_0 enters as c_{-1}; deeper ghosts zero
            sC[tid] = (tid == NGH - 1) ? make_float2(x0_in[0], x0_in[1])
                                       : make_float2(0.f, 0.f);
        } else {
            int start = chunk - LT * (tid + 1);
            float ga = 0.f, gb = 0.f;
#pragma unroll
            for (int i = 0; i < LT; i++) {
                float u0v = U0[start + i];
                float u1v = U1[start + i];
                STEPV(ga, gb, u0v, u1v);
            }
            sC[NGH - 1 - tid] = make_float2(ga, gb);   // c_{-(tid+1)}
        }
    }
    __syncthreads();

    // ---- Load own u data once into registers (kept for both phases) --------
    float4 p[2], q[2];
#pragma unroll
    for (int s = 0; s < 2; s++) {
        p[s] = sA[idxU(tid, s)];
        q[s] = sA[256 + idxU(tid, s)];
    }

    // ---- Phase 1: 8-step zero-init scan ------------------------------------
    {
        float za = 0.f, zb = 0.f;
#pragma unroll
        for (int s = 0; s < 2; s++) {
            STEPV(za, zb, p[s].x, q[s].x);
            STEPV(za, zb, p[s].y, q[s].y);
            STEPV(za, zb, p[s].z, q[s].z);
            STEPV(za, zb, p[s].w, q[s].w);
        }
        sC[NGH + tid] = make_float2(za, zb);
    }

    // ---- Powers: A^8 (3 squarings), A^16, A^24, A^32, A^40 -----------------
    float m00 = a00, m01 = a01, m10 = a10, m11 = a11;   // -> A^8
#pragma unroll
    for (int s = 0; s < 3; s++) {
        float tr  = m00 + m11;
        float det = m01 * m10;
        float t00 = fmaf(m00, m00, det);
        float t01 = m01 * tr;
        float t10 = m10 * tr;
        float t11 = fmaf(m11, m11, det);
        m00 = t00; m01 = t01; m10 = t10; m11 = t11;
    }
    float n00, n01, n10, n11;                            // A^16
    MATMUL(n00,n01,n10,n11, m00,m01,m10,m11, m00,m01,m10,m11);
    float r00, r01, r10, r11;                            // A^24
    MATMUL(r00,r01,r10,r11, n00,n01,n10,n11, m00,m01,m10,m11);
    float s00, s01, s10, s11;                            // A^32
    MATMUL(s00,s01,s10,s11, n00,n01,n10,n11, n00,n01,n10,n11);
    float t00, t01, t10, t11;                            // A^40
    MATMUL(t00,t01,t10,t11, s00,s01,s10,s11, m00,m01,m10,m11);

    __syncthreads();   // sC ready; all sA reads done -> overlay safe below

    // ---- Carry combine: S = c1 + A^8 c2 + A^16 c3 + A^24 c4 + A^32 c5 + A^40 c6
    float xa, xb;
    {
        float2 c1 = sC[tid + 5];
        float2 c2 = sC[tid + 4];
        float2 c3 = sC[tid + 3];
        float2 c4 = sC[tid + 2];
        float2 c5 = sC[tid + 1];
        float2 c6 = sC[tid];
        xa = c1.x
           + fmaf(m00, c2.x, m01 * c2.y)
           + fmaf(n00, c3.x, n01 * c3.y)
           + fmaf(r00, c4.x, r01 * c4.y)
           + fmaf(s00, c5.x, s01 * c5.y)
           + fmaf(t00, c6.x, t01 * c6.y);
        xb = c1.y
           + fmaf(m10, c2.x, m11 * c2.y)
           + fmaf(n10, c3.x, n11 * c3.y)
           + fmaf(r10, c4.x, r11 * c4.y)
           + fmaf(s10, c5.x, s11 * c5.y)
           + fmaf(t10, c6.x, t11 * c6.y);
    }

    // ---- Phase 2: rescan from regs; outputs -> overlay plane (sA) ----------
#pragma unroll
    for (int s = 0; s < 2; s++) {
        float4 d = sDT[idxU(tid, s)];
        float4 oA, oB;
#define EMIT(U0v, U1v, DTv, O0, O1)                                 \
        do {                                                        \
            float pre0 = xa, pre1 = xb;                             \
            STEPV(xa, xb, U0v, U1v);                                \
            float s_, c_;                                           \
            __sincosf((U1v), &s_, &c_);                             \
            float cc = (U0v) * (DTv);                               \
            O0 = fmaf(cc, c_, pre0) - xa;                           \
            O1 = fmaf(cc, s_, pre1) - xb;                           \
        } while (0)
        EMIT(p[s].x, q[s].x, d.x, oA.x, oA.y);
        EMIT(p[s].y, q[s].y, d.y, oA.z, oA.w);
        EMIT(p[s].z, q[s].z, d.z, oB.x, oB.y);
        EMIT(p[s].w, q[s].w, d.w, oB.z, oB.w);
#undef EMIT
        sA[idxO(tid, 2 * s)]     = oA;
        sA[idxO(tid, 2 * s + 1)] = oB;
    }
    __syncthreads();

    // ---- Coalesced STG.128 of outputs --------------------------------------
    {
        float4* og = reinterpret_cast<float4*>(out + 2 * chunk);
#pragma unroll
        for (int k = 0; k < 4; k++) {
            int h = k * TPB + tid;            // 0..511
            og[h] = sA[idxO(h >> 2, h & 3)];
        }
    }
#undef STEPV
}

extern "C" void kernel_launch(void* const* d_in, const int* in_sizes, int n_in,
                              void* d_out, int out_size)
{
    const float* x0 = (const float*)d_in[0];   // (1,2)
    const float* u  = (const float*)d_in[1];   // (2,T)
    const float* dt = (const float*)d_in[2];   // (T,)
    const float* WA = (const float*)d_in[3];   // (2,2)
    const float* bA = (const float*)d_in[4];   // (2,)
    const float* WB = (const float*)d_in[5];   // (2,2)
    const float* bB = (const float*)d_in[6];   // (2,)
    float* out = (float*)d_out;                // (T,2)

    int T = in_sizes[2];
    int grid = (T + CHUNK - 1) / CHUNK;        // 2^22 / 1024 = 4096 blocks

    pinn_rnn_kernel<<<grid, TPB>>>(x0, u, dt, WA, bA, WB, bB, out, T);
}